// round 16
// baseline (speedup 1.0000x reference)
#include <cuda_runtime.h>
#include <cuda_fp16.h>
#include <cstdint>
#include <math.h>

// ================= problem constants =================
#define NB 2048
#define NH 1024
#define NDIN 1920
#define BAND 96          // GEMM band half-width
#define AWRITE 256       // adjacency write half-width (covers GEMM reads)
#define ASUM 512         // adjacency row-sum half-width (tail < e^-51)

typedef __half f16;

// ================= device scratch (no allocations allowed) =================
__device__ __align__(16) float g_h[(size_t)NB * NH];
__device__ __align__(16) float g_k1[(size_t)NB * NH];
__device__ __align__(16) float g_k2[(size_t)NB * NH];
__device__ __align__(16) float g_k3[(size_t)NB * NH];
__device__ __align__(16) float g_t[(size_t)NB * NH];

__device__ __align__(16) f16 g_adj_hi[(size_t)NB * NB];
__device__ __align__(16) f16 g_f_hi[(size_t)NB * NDIN];
__device__ __align__(16) f16 g_wpT_hi[(size_t)NH * NDIN];
__device__ __align__(16) f16 g_w1aT_hi[(size_t)NH * NH];
__device__ __align__(16) f16 g_w1bT_hi[(size_t)NH * NH];
__device__ __align__(16) f16 g_w2T_hi[(size_t)NH * NH];
__device__ __align__(16) f16 g_hs_hi[(size_t)NB * NH];
__device__ __align__(16) f16 g_ns_hi[(size_t)NB * NH];
__device__ __align__(16) f16 g_zs_hi[(size_t)NB * NH];

// software grid barrier state (generation-based; replay-safe)
__device__ volatile unsigned g_barc = 0;
__device__ volatile unsigned g_barg = 0;

// ================= PTX helpers (arch-suffix-free only) =================
__device__ __forceinline__ uint32_t smem_u32(const void* p) {
    uint32_t a;
    asm("{ .reg .u64 t; cvta.to.shared.u64 t, %1; cvt.u32.u64 %0, t; }"
        : "=r"(a) : "l"(p));
    return a;
}

__device__ __forceinline__ void cp16(uint32_t sdst, const void* gsrc) {
    asm volatile("cp.async.cg.shared.global [%0], [%1], 16;"
                 :: "r"(sdst), "l"(gsrc) : "memory");
}
#define CP_COMMIT() asm volatile("cp.async.commit_group;" ::: "memory")
#define CP_WAIT(n)  asm volatile("cp.async.wait_group %0;" :: "n"(n) : "memory")

__device__ __forceinline__ void ldsm_x4(uint32_t (&r)[4], uint32_t addr) {
    asm volatile("ldmatrix.sync.aligned.m8n8.x4.shared.b16 {%0,%1,%2,%3}, [%4];"
                 : "=r"(r[0]), "=r"(r[1]), "=r"(r[2]), "=r"(r[3]) : "r"(addr));
}

__device__ __forceinline__ void ldsm_x4_trans(uint32_t (&r)[4], uint32_t addr) {
    asm volatile("ldmatrix.sync.aligned.m8n8.x4.trans.shared.b16 {%0,%1,%2,%3}, [%4];"
                 : "=r"(r[0]), "=r"(r[1]), "=r"(r[2]), "=r"(r[3]) : "r"(addr));
}

__device__ __forceinline__ void mma16816(float (&c)[4], const uint32_t (&a)[4],
                                         uint32_t b0, uint32_t b1) {
    asm volatile(
        "mma.sync.aligned.m16n8k16.row.col.f32.f16.f16.f32 "
        "{%0,%1,%2,%3}, {%4,%5,%6,%7}, {%8,%9}, {%0,%1,%2,%3};"
        : "+f"(c[0]), "+f"(c[1]), "+f"(c[2]), "+f"(c[3])
        : "r"(a[0]), "r"(a[1]), "r"(a[2]), "r"(a[3]), "r"(b0), "r"(b1));
}

__device__ __forceinline__ void grid_sync(int nblk) {
    __syncthreads();
    if (threadIdx.x == 0) {
        const unsigned gen = g_barg;
        __threadfence();
        if (atomicAdd((unsigned*)&g_barc, 1u) == (unsigned)(nblk - 1)) {
            g_barc = 0;
            __threadfence();
            g_barg = gen + 1;
        } else {
            while (g_barg == gen) { }
        }
        __threadfence();
    }
    __syncthreads();
}

// ================= in-kernel setup jobs =================
// banded fp16 adjacency row (256 threads; red = smem scratch of 256 floats)
__device__ void adj_row(int i, const int* __restrict__ spk,
                        const float* __restrict__ mm, f16* __restrict__ adjh,
                        float* red, int tid)
{
    const int si = spk[i];
    const float m0 = mm[i * 3 + 0], m1 = mm[i * 3 + 1], m2 = mm[i * 3 + 2];

    const int jLoS = (i > ASUM) ? i - ASUM : 0;
    const int jHiS = (i + ASUM + 1 < NB) ? i + ASUM + 1 : NB;

    float lsum = 0.f;
    for (int j = jLoS + tid; j < jHiS; j += 256) {
        float v;
        if (j == i) v = 1.0f;
        else {
            float tw = expf(-0.1f * fabsf((float)(i - j)));
            if (spk[j] == si) v = 0.8f * tw;
            else {
                float md = (fabsf(m0 - mm[j * 3 + 0]) + fabsf(m1 - mm[j * 3 + 1]) +
                            fabsf(m2 - mm[j * 3 + 2])) * (1.0f / 3.0f);
                v = 0.5f * tw * (1.0f - md);
            }
        }
        lsum += v;
    }
    red[tid] = lsum;
    __syncthreads();
    for (int s = 128; s > 0; s >>= 1) {
        if (tid < s) red[tid] += red[tid + s];
        __syncthreads();
    }
    const float inv = 1.0f / (red[0] + 1e-8f);
    __syncthreads();   // red reuse safety across rows

    const int jLoW = (i > AWRITE) ? i - AWRITE : 0;
    const int jHiW = (i + AWRITE + 1 < NB) ? i + AWRITE + 1 : NB;
    for (int j = jLoW + tid; j < jHiW; j += 256) {
        float v;
        if (j == i) v = 1.0f;
        else {
            float tw = expf(-0.1f * fabsf((float)(i - j)));
            if (spk[j] == si) v = 0.8f * tw;
            else {
                float md = (fabsf(m0 - mm[j * 3 + 0]) + fabsf(m1 - mm[j * 3 + 1]) +
                            fabsf(m2 - mm[j * 3 + 2])) * (1.0f / 3.0f);
                v = 0.5f * tw * (1.0f - md);
            }
        }
        adjh[(size_t)i * NB + j] = __float2half_rn(v * inv);
    }
}

// one 32x32 transpose tile: src [R][C] fp32 -> dst [C][R] f16
// tileIdx = ty0 * (C/32) + tx0 ; threads laid out tx=tid&31, ty=tid>>5 (8 rows)
__device__ void transpose_tile(const float* __restrict__ src, int R, int C,
                               f16* __restrict__ dst, int tileIdx,
                               float* tile /* [32][33] smem */, int tid)
{
    const int tilesX = C >> 5;
    const int r0 = (tileIdx / tilesX) << 5;
    const int c0 = (tileIdx % tilesX) << 5;
    const int tx = tid & 31, ty = tid >> 5;
#pragma unroll
    for (int d = 0; d < 4; d++) {
        int r = r0 + ty + d * 8;
        tile[(ty + d * 8) * 33 + tx] = src[(size_t)r * C + c0 + tx];
    }
    __syncthreads();
#pragma unroll
    for (int d = 0; d < 4; d++) {
        int cc = c0 + ty + d * 8;
        dst[(size_t)cc * R + r0 + tx] = __float2half_rn(tile[tx * 33 + ty + d * 8]);
    }
    __syncthreads();
}

// ============ fp16 GEMM tile machinery: 64x128 tile, 3-stage ============
#define MT 64
#define NT 128
#define LDT 40
#define LDBT 136
#define SUBA (MT * LDT * 2)       // 5120 B
#define SUBB (NT * LDT * 2)       // 10240 B
#define NSTAGE 3
#define STG  (SUBA + SUBB)        // 15360 B
#define GDYN (NSTAGE * STG)       // 46080 B

#define NTILES (NB / MT * (NH / NT))   // 256

struct GemmDesc {
    const f16* A;
    const f16* B;
    int K, lda, ldb, btrans, band;
    float* Ck;
    float* Chn;
    f16*   outHi;
    const float* bias;
    const float* addC;
    int do_tanh;
    const float *cmb_h, *cmb_ka, *cmb_kb, *cmb_kc;
    float ca, cb, cc, cv;
};

__device__ __forceinline__ void stage_load(uint32_t sstage,
                                           const f16* A, const f16* B,
                                           int lda, int ldb, int cRow, int cCol,
                                           int k0, int tid, int btrans)
{
    {
        const int r = tid >> 2;
        const int c16 = tid & 3;
        const uint32_t sd = sstage + r * (LDT * 2) + c16 * 16;
        const char* gs = (const char*)(A + (size_t)(cRow + r) * lda + k0) + c16 * 16;
        cp16(sd, gs);
    }
    if (!btrans) {
#pragma unroll
        for (int i = 0; i < 2; i++) {
            const int cid = tid + (i << 8);
            const int r = cid >> 2;
            const int c16 = cid & 3;
            const uint32_t sd = sstage + SUBA + r * (LDT * 2) + c16 * 16;
            const char* gs = (const char*)(B + (size_t)(cCol + r) * ldb + k0) + c16 * 16;
            cp16(sd, gs);
        }
    } else {
#pragma unroll
        for (int i = 0; i < 2; i++) {
            const int cid = tid + (i << 8);
            const int r = cid >> 4;
            const int c16 = cid & 15;
            const uint32_t sd = sstage + SUBA + r * (LDBT * 2) + c16 * 16;
            const char* gs = (const char*)(B + (size_t)(k0 + r) * ldb + cCol) + c16 * 16;
            cp16(sd, gs);
        }
    }
}

__device__ __forceinline__ void tile_mma(uint32_t sstage, int wm, int wn,
                                         int lane, float (&c)[2][4][4], int btrans)
{
    const uint32_t aS = sstage;
    const uint32_t bS = sstage + SUBA;
    const int arow = wm * 32 + (lane & 15);
    const int acolg = (lane >> 4) * 8;
    const int brow = (lane & 7) + ((lane >> 4) << 3);
    const int bcolg = ((lane >> 3) & 1) * 8;
    const int trow = lane & 15;
    const int tcol = (lane >> 4) * 8;
#pragma unroll
    for (int ks = 0; ks < 2; ks++) {
        const int kofs = ks * 16;
        uint32_t a[2][4];
#pragma unroll
        for (int mi = 0; mi < 2; mi++) {
            const uint32_t off = (uint32_t)(arow + mi * 16) * (LDT * 2) +
                                 (kofs + acolg) * 2;
            ldsm_x4(a[mi], aS + off);
        }
        uint32_t b[2][4];
        if (!btrans) {
#pragma unroll
            for (int ni = 0; ni < 2; ni++) {
                const uint32_t off = (uint32_t)(wn * 32 + ni * 16 + brow) * (LDT * 2) +
                                     (kofs + bcolg) * 2;
                ldsm_x4(b[ni], bS + off);
            }
        } else {
#pragma unroll
            for (int ni = 0; ni < 2; ni++) {
                const uint32_t off = (uint32_t)(kofs + trow) * (LDBT * 2) +
                                     (wn * 32 + ni * 16 + tcol) * 2;
                ldsm_x4_trans(b[ni], bS + off);
            }
        }
#pragma unroll
        for (int mi = 0; mi < 2; mi++) {
#pragma unroll
            for (int nj = 0; nj < 4; nj++) {
                mma16816(c[mi][nj], a[mi],
                         b[nj >> 1][(nj & 1) * 2], b[nj >> 1][(nj & 1) * 2 + 1]);
            }
        }
    }
}

__device__ void run_tile(const GemmDesc& d, int tile, uint32_t sbase, int tid)
{
    const int wid = tid >> 5;
    const int lane = tid & 31;
    const int wm = wid >> 2;
    const int wn = wid & 3;
    const int cRow = (tile >> 3) * MT;
    const int cCol = (tile & 7) * NT;

    float c[2][4][4] = {};

    int kLo = 0, kHi = d.K;
    if (d.band) {
        kLo = (cRow > BAND) ? ((cRow - BAND) & ~31) : 0;
        const int hi = cRow + MT + BAND;
        kHi = (hi < d.K) ? ((hi + 31) & ~31) : d.K;
    }
    const int nt = (kHi - kLo) >> 5;

#pragma unroll
    for (int p = 0; p < NSTAGE - 1; p++) {
        if (p < nt) {
            stage_load(sbase + (uint32_t)p * STG, d.A, d.B,
                       d.lda, d.ldb, cRow, cCol, kLo + p * 32, tid, d.btrans);
            CP_COMMIT();
        }
    }
    for (int it = 0; it < nt; it++) {
        if (it + 1 < nt) { CP_WAIT(1); } else { CP_WAIT(0); }
        __syncthreads();
        if (it + NSTAGE - 1 < nt) {
            stage_load(sbase + (uint32_t)((it + NSTAGE - 1) % NSTAGE) * STG,
                       d.A, d.B, d.lda, d.ldb, cRow, cCol,
                       kLo + (it + NSTAGE - 1) * 32, tid, d.btrans);
            CP_COMMIT();
        }
        tile_mma(sbase + (uint32_t)(it % NSTAGE) * STG, wm, wn, lane, c, d.btrans);
    }
    __syncthreads();

    const int row0 = cRow + wm * 32;
    const int col0 = cCol + wn * 32;
#pragma unroll
    for (int mi = 0; mi < 2; mi++) {
#pragma unroll
        for (int nj = 0; nj < 4; nj++) {
            const int r = row0 + mi * 16 + (lane >> 2);
            const int col = col0 + nj * 8 + (lane & 3) * 2;
            const size_t i0 = (size_t)r * NH + col;
            const size_t i1 = (size_t)(r + 8) * NH + col;
            float2 bv = make_float2(0.f, 0.f);
            if (d.bias) bv = *(const float2*)(d.bias + col);
            float v0 = c[mi][nj][0] + bv.x;
            float v1 = c[mi][nj][1] + bv.y;
            float v2 = c[mi][nj][2] + bv.x;
            float v3 = c[mi][nj][3] + bv.y;
            if (d.addC) {
                float2 x0 = *(const float2*)(d.addC + i0);
                float2 x1 = *(const float2*)(d.addC + i1);
                v0 += x0.x; v1 += x0.y; v2 += x1.x; v3 += x1.y;
            }
            if (d.do_tanh) {
                v0 = tanhf(v0); v1 = tanhf(v1);
                v2 = tanhf(v2); v3 = tanhf(v3);
            }
            float o0 = v0, o1 = v1, o2 = v2, o3 = v3;
            if (d.cmb_h) {
                float2 h0 = *(const float2*)(d.cmb_h + i0);
                float2 h1 = *(const float2*)(d.cmb_h + i1);
                float2 a0 = *(const float2*)(d.cmb_ka + i0);
                float2 a1 = *(const float2*)(d.cmb_ka + i1);
                float2 e0 = *(const float2*)(d.cmb_kb + i0);
                float2 e1 = *(const float2*)(d.cmb_kb + i1);
                float2 q0 = *(const float2*)(d.cmb_kc + i0);
                float2 q1 = *(const float2*)(d.cmb_kc + i1);
                o0 = h0.x + d.ca * a0.x + d.cb * e0.x + d.cc * q0.x + d.cv * v0;
                o1 = h0.y + d.ca * a0.y + d.cb * e0.y + d.cc * q0.y + d.cv * v1;
                o2 = h1.x + d.ca * a1.x + d.cb * e1.x + d.cc * q1.x + d.cv * v2;
                o3 = h1.y + d.ca * a1.y + d.cb * e1.y + d.cc * q1.y + d.cv * v3;
            }
            if (d.Ck) {
                *(float2*)(d.Ck + i0) = make_float2(v0, v1);
                *(float2*)(d.Ck + i1) = make_float2(v2, v3);
            }
            if (d.Chn) {
                *(float2*)(d.Chn + i0) = make_float2(o0, o1);
                *(float2*)(d.Chn + i1) = make_float2(o2, o3);
            }
            if (d.outHi) {
                *(__half2*)(d.outHi + i0) =
                    __halves2half2(__float2half_rn(o0), __float2half_rn(o1));
                *(__half2*)(d.outHi + i1) =
                    __halves2half2(__float2half_rn(o2), __float2half_rn(o3));
            }
        }
    }
}

// ================= single persistent mega-kernel =================
#define WP_TILES ((NH / 32) * (NDIN / 32))   // 1920
#define W_TILES  ((NH / 32) * (NH / 32))     // 1024
#define CVT_CHUNKS ((NB * NDIN) / (256 * 4)) // 3840

__global__ __launch_bounds__(256, 2)
void mega_kernel(const float* __restrict__ features, const int* __restrict__ spk,
                 const float* __restrict__ mm,
                 const float* __restrict__ W_proj, const float* __restrict__ W1,
                 const float* __restrict__ W2,
                 const float* __restrict__ b_proj, const float* __restrict__ b1,
                 const float* __restrict__ b2,
                 f16* __restrict__ f_hi, f16* __restrict__ wpT,
                 f16* __restrict__ adj, f16* __restrict__ w1aT,
                 f16* __restrict__ w1bT, f16* __restrict__ w2T,
                 float* __restrict__ h, float* __restrict__ k1,
                 float* __restrict__ k2, float* __restrict__ k3,
                 float* __restrict__ t,
                 f16* __restrict__ hs, f16* __restrict__ ns, f16* __restrict__ zs,
                 float* __restrict__ out)
{
    extern __shared__ char sm[];
    const uint32_t sbase = smem_u32(sm);
    float* fsm = (float*)sm;                 // scratch views of dynamic smem
    const int tid = threadIdx.x;
    const int bid = blockIdx.x;
    const int nblk = gridDim.x;

    // ---- phase -1: all setup in parallel ----
    {
        // feature convert: 3840 chunks of 1024 elems
        for (int ch = bid; ch < CVT_CHUNKS; ch += nblk) {
            const int i = (ch * 256 + tid) * 4;
            float4 v = *(const float4*)(features + i);
            *(__half2*)(f_hi + i)     = __halves2half2(__float2half_rn(v.x), __float2half_rn(v.y));
            *(__half2*)(f_hi + i + 2) = __halves2half2(__float2half_rn(v.z), __float2half_rn(v.w));
        }
        // weight transposes: 4992 tiles
        const int T0 = WP_TILES, T1 = T0 + W_TILES, T2 = T1 + W_TILES, T3 = T2 + W_TILES;
        for (int w = bid; w < T3; w += nblk) {
            if (w < T0)      transpose_tile(W_proj, NDIN, NH, wpT, w, fsm, tid);
            else if (w < T1) transpose_tile(W1, NH, NH, w1aT, w - T0, fsm, tid);
            else if (w < T2) transpose_tile(W1 + (size_t)NH * NH, NH, NH, w1bT, w - T1, fsm, tid);
            else             transpose_tile(W2, NH, NH, w2T, w - T2, fsm, tid);
        }
        // banded adjacency: 2048 rows
        for (int i = bid; i < NB; i += nblk)
            adj_row(i, spk, mm, adj, fsm, tid);
    }
    grid_sync(nblk);

    // ---- phase 0: h0 = f @ wpT + b_proj ----
    {
        GemmDesc d = {};
        d.A = f_hi; d.B = wpT; d.K = NDIN; d.lda = NDIN; d.ldb = NDIN;
        d.Ck = h; d.outHi = hs; d.bias = b_proj;
        for (int tl = bid; tl < NTILES; tl += nblk) run_tile(d, tl, sbase, tid);
    }
    grid_sync(nblk);

    const float third = 1.0f / 3.0f;
    const float CA[4] = {0.f, -third, 1.f, 0.125f};
    const float CB[4] = {0.f, 0.f, -1.f, 0.375f};
    const float CC[4] = {0.f, 0.f, 0.f, 0.375f};
    const float CV[4] = {third, 1.f, 1.f, 0.125f};
    float* kout[4] = {k1, k2, k3, nullptr};

    for (int e = 0; e < 4; e++) {
        // ---- phase A: t = hs @ W1a  ||  ns = adj @ hs (banded) ----
        {
            GemmDesc dW1a = {};
            dW1a.A = hs; dW1a.B = w1aT; dW1a.K = NH; dW1a.lda = NH; dW1a.ldb = NH;
            dW1a.Ck = t;
            GemmDesc dAdj = {};
            dAdj.A = adj; dAdj.B = hs; dAdj.K = NB; dAdj.lda = NB; dAdj.ldb = NH;
            dAdj.btrans = 1; dAdj.band = 1; dAdj.outHi = ns;
            for (int tl = bid; tl < 2 * NTILES; tl += nblk) {
                if (tl < NTILES) run_tile(dW1a, tl, sbase, tid);
                else             run_tile(dAdj, tl - NTILES, sbase, tid);
            }
        }
        grid_sync(nblk);

        // ---- phase B: zs = tanh(t + ns @ W1b + b1) ----
        {
            GemmDesc d = {};
            d.A = ns; d.B = w1bT; d.K = NH; d.lda = NH; d.ldb = NH;
            d.outHi = zs; d.bias = b1; d.addC = t; d.do_tanh = 1;
            for (int tl = bid; tl < NTILES; tl += nblk) run_tile(d, tl, sbase, tid);
        }
        grid_sync(nblk);

        // ---- phase C: k_e = zs @ W2 + b2 ; htmp/out combine ----
        {
            GemmDesc d = {};
            d.A = zs; d.B = w2T; d.K = NH; d.lda = NH; d.ldb = NH;
            d.Ck = kout[e];
            d.Chn = (e == 3) ? out : nullptr;
            d.outHi = (e == 3) ? nullptr : hs;
            d.bias = b2;
            d.cmb_h = h; d.cmb_ka = k1; d.cmb_kb = k2; d.cmb_kc = k3;
            d.ca = CA[e]; d.cb = CB[e]; d.cc = CC[e]; d.cv = CV[e];
            for (int tl = bid; tl < NTILES; tl += nblk) run_tile(d, tl, sbase, tid);
        }
        if (e < 3) grid_sync(nblk);
    }
}

// ================= host orchestration =================
extern "C" void kernel_launch(void* const* d_in, const int* in_sizes, int n_in,
                              void* d_out, int out_size)
{
    const float* features = (const float*)d_in[0];
    const int*   spk      = (const int*)  d_in[1];
    const float* mm       = (const float*)d_in[2];
    const float* W_proj   = (const float*)d_in[3];
    const float* b_proj   = (const float*)d_in[4];
    const float* W1       = (const float*)d_in[5];
    const float* b1       = (const float*)d_in[6];
    const float* W2       = (const float*)d_in[7];
    const float* b2       = (const float*)d_in[8];
    float* out = (float*)d_out;

    cudaFuncSetAttribute(mega_kernel,
                         cudaFuncAttributeMaxDynamicSharedMemorySize, GDYN);

    float *h, *k1, *k2, *k3, *t;
    f16 *adj, *f_hi, *wpT, *w1aT, *w1bT, *w2T, *hs, *ns, *zs;
    cudaGetSymbolAddress((void**)&h,  g_h);
    cudaGetSymbolAddress((void**)&k1, g_k1);
    cudaGetSymbolAddress((void**)&k2, g_k2);
    cudaGetSymbolAddress((void**)&k3, g_k3);
    cudaGetSymbolAddress((void**)&t,  g_t);
    cudaGetSymbolAddress((void**)&adj,  g_adj_hi);
    cudaGetSymbolAddress((void**)&f_hi, g_f_hi);
    cudaGetSymbolAddress((void**)&wpT,  g_wpT_hi);
    cudaGetSymbolAddress((void**)&w1aT, g_w1aT_hi);
    cudaGetSymbolAddress((void**)&w1bT, g_w1bT_hi);
    cudaGetSymbolAddress((void**)&w2T,  g_w2T_hi);
    cudaGetSymbolAddress((void**)&hs,   g_hs_hi);
    cudaGetSymbolAddress((void**)&ns,   g_ns_hi);
    cudaGetSymbolAddress((void**)&zs,   g_zs_hi);

    // grid size: guaranteed co-resident (required for the software barrier)
    int nsm = 0, occ = 0;
    cudaDeviceGetAttribute(&nsm, cudaDevAttrMultiProcessorCount, 0);
    cudaOccupancyMaxActiveBlocksPerMultiprocessor(&occ, mega_kernel, 256, GDYN);
    int nblk = nsm * occ;
    if (nblk > NTILES) nblk = NTILES;
    if (nblk < 1) nblk = 1;

    // ---- the whole problem in one persistent kernel ----
    mega_kernel<<<nblk, 256, GDYN>>>(features, spk, mm, W_proj, W1, W2,
                                     b_proj, b1, b2,
                                     f_hi, wpT, adj, w1aT, w1bT, w2T,
                                     h, k1, k2, k3, t, hs, ns, zs, out);
}